// round 3
// baseline (speedup 1.0000x reference)
#include <cuda_runtime.h>
#include <float.h>

#define IN_DIM 256
#define OUT_DIM 512
#define MEM_LEN 131072
#define TOPK 16

#define ENC_PARTS 32
#define ROWS_PER_PART (IN_DIM / ENC_PARTS)   // 8

#define ROWS_PER_BLOCK 256
#define DIST_BLOCKS (MEM_LEN / ROWS_PER_BLOCK)   // 512
#define DIST_NT 512
#define DIST_ITERS (ROWS_PER_BLOCK / (DIST_NT / 32))  // 16

#define CAND_N (DIST_BLOCKS * TOPK)          // 8192
#define FIN_NT 256

__device__ float g_enc[OUT_DIM];
__device__ float g_part[ENC_PARTS * OUT_DIM];
__device__ float g_cand[CAND_N];

// ---------------------------------------------------------------------------
// Kernel A1: partial GEMV. Block p covers input rows [p*8, p*8+8).
// ---------------------------------------------------------------------------
__global__ void enc_partial_kernel(const float* __restrict__ data,
                                   const float* __restrict__ mean,
                                   const float* __restrict__ stdv,
                                   const float* __restrict__ W) {
    __shared__ float xn[ROWS_PER_PART];
    int t = threadIdx.x;              // 0..511 = output column
    int r0 = blockIdx.x * ROWS_PER_PART;
    if (t < ROWS_PER_PART) {
        int r = r0 + t;
        float s = stdv[r];
        xn[t] = (s == 0.0f) ? 0.0f : (data[r] - mean[r]) / s;
    }
    __syncthreads();
    float acc = 0.0f;
#pragma unroll
    for (int i = 0; i < ROWS_PER_PART; ++i)
        acc = fmaf(xn[i], W[(size_t)(r0 + i) * OUT_DIM + t], acc);
    g_part[blockIdx.x * OUT_DIM + t] = acc;
}

// ---------------------------------------------------------------------------
// Kernel A2: reduce partials, add bias, tanh.
// ---------------------------------------------------------------------------
__global__ void enc_finish_kernel(const float* __restrict__ b) {
    int t = threadIdx.x;
    float acc = b[t];
#pragma unroll
    for (int p = 0; p < ENC_PARTS; ++p)
        acc += g_part[p * OUT_DIM + t];
    g_enc[t] = tanhf(acc);
}

// ---------------------------------------------------------------------------
// Kernel B: fused dist + per-block top-16.
// 512 blocks x 512 threads; 16 warps x 16 iterations = 256 rows/block.
// L1 distances land in shared, then an in-block bitonic sort over 256
// emits the block's 16 smallest into g_cand (exact: rows are disjoint).
// ---------------------------------------------------------------------------
__global__ void dist_topk_kernel(const float* __restrict__ memory) {
    __shared__ float se[OUT_DIM];
    __shared__ float sdist[ROWS_PER_BLOCK];

    int t = threadIdx.x;
    se[t] = g_enc[t];
    __syncthreads();

    int warp = t >> 5;
    int lane = t & 31;

    const float4* es = (const float4*)se;
    float4 e0 = es[0 * 32 + lane];
    float4 e1 = es[1 * 32 + lane];
    float4 e2 = es[2 * 32 + lane];
    float4 e3 = es[3 * 32 + lane];

    size_t row0 = (size_t)blockIdx.x * ROWS_PER_BLOCK;

#pragma unroll 2
    for (int it = 0; it < DIST_ITERS; ++it) {
        int r = it * 16 + warp;                       // 0..255
        const float4* m = (const float4*)(memory + (row0 + r) * OUT_DIM);
        float4 v0 = __ldg(&m[0 * 32 + lane]);
        float4 v1 = __ldg(&m[1 * 32 + lane]);
        float4 v2 = __ldg(&m[2 * 32 + lane]);
        float4 v3 = __ldg(&m[3 * 32 + lane]);

        float s = 0.0f;
        s += fabsf(v0.x - e0.x) + fabsf(v0.y - e0.y) + fabsf(v0.z - e0.z) + fabsf(v0.w - e0.w);
        s += fabsf(v1.x - e1.x) + fabsf(v1.y - e1.y) + fabsf(v1.z - e1.z) + fabsf(v1.w - e1.w);
        s += fabsf(v2.x - e2.x) + fabsf(v2.y - e2.y) + fabsf(v2.z - e2.z) + fabsf(v2.w - e2.w);
        s += fabsf(v3.x - e3.x) + fabsf(v3.y - e3.y) + fabsf(v3.z - e3.z) + fabsf(v3.w - e3.w);

#pragma unroll
        for (int o = 16; o > 0; o >>= 1)
            s += __shfl_xor_sync(0xFFFFFFFFu, s, o);

        if (lane == 0) sdist[r] = s;
    }
    __syncthreads();

    // bitonic sort ascending over 256 values (threads 0..255 active per phase)
    for (int k = 2; k <= ROWS_PER_BLOCK; k <<= 1) {
        for (int j = k >> 1; j > 0; j >>= 1) {
            if (t < ROWS_PER_BLOCK) {
                int ixj = t ^ j;
                if (ixj > t) {
                    float a = sdist[t], c = sdist[ixj];
                    bool up = ((t & k) == 0);
                    if ((a > c) == up) { sdist[t] = c; sdist[ixj] = a; }
                }
            }
            __syncthreads();
        }
    }

    if (t < TOPK)
        g_cand[blockIdx.x * TOPK + t] = sdist[t];
}

// ---------------------------------------------------------------------------
// Kernel C: exact top-16 of the 8192 candidates + weighted loss.
// Per-thread sorted insertion over 32 values, then 8-level merge tree.
// ---------------------------------------------------------------------------
__global__ void final_topk_kernel(const float* __restrict__ exp_w,
                                  float* __restrict__ out) {
    __shared__ float sh[FIN_NT * TOPK];
    int tid = threadIdx.x;
    float* mine = sh + tid * TOPK;

#pragma unroll
    for (int i = 0; i < TOPK; ++i) mine[i] = FLT_MAX;

    for (int idx = tid; idx < CAND_N; idx += FIN_NT) {
        float v = g_cand[idx];
        if (v < mine[TOPK - 1]) {
            int j = TOPK - 1;
            while (j > 0 && mine[j - 1] > v) {
                mine[j] = mine[j - 1];
                --j;
            }
            mine[j] = v;
        }
    }

    for (int s = FIN_NT / 2; s >= 1; s >>= 1) {
        __syncthreads();
        if (tid < s) {
            float* a = sh + tid * TOPK;
            float* c = sh + (tid + s) * TOPK;
            float merged[TOPK];
            int ia = 0, ib = 0;
#pragma unroll
            for (int i = 0; i < TOPK; ++i) {
                float av = a[ia];
                float bv = c[ib];
                if (av <= bv) { merged[i] = av; ++ia; }
                else          { merged[i] = bv; ++ib; }
            }
#pragma unroll
            for (int i = 0; i < TOPK; ++i) a[i] = merged[i];
        }
    }
    __syncthreads();

    if (tid == 0) {
        float num = 0.0f, den = 0.0f;
#pragma unroll
        for (int i = 0; i < TOPK; ++i) {
            float w = exp_w[i];
            num = fmaf(sh[i], w, num);
            den += w;
        }
        out[0] = num / den;
    }
}

// ---------------------------------------------------------------------------
// Launch.
// Inputs: data[256], mean[256], std[256], memory[131072*512],
//         W[256*512], b[512], exp_w[16]  ->  out[1] float
// ---------------------------------------------------------------------------
extern "C" void kernel_launch(void* const* d_in, const int* in_sizes, int n_in,
                              void* d_out, int out_size) {
    const float* data   = (const float*)d_in[0];
    const float* mean   = (const float*)d_in[1];
    const float* stdv   = (const float*)d_in[2];
    const float* memory = (const float*)d_in[3];
    const float* W      = (const float*)d_in[4];
    const float* b      = (const float*)d_in[5];
    const float* exp_w  = (const float*)d_in[6];
    float* out = (float*)d_out;

    enc_partial_kernel<<<ENC_PARTS, OUT_DIM>>>(data, mean, stdv, W);
    enc_finish_kernel<<<1, OUT_DIM>>>(b);
    dist_topk_kernel<<<DIST_BLOCKS, DIST_NT>>>(memory);
    final_topk_kernel<<<1, FIN_NT>>>(exp_w, out);
}

// round 4
// speedup vs baseline: 1.5507x; 1.5507x over previous
#include <cuda_runtime.h>
#include <float.h>

#define IN_DIM 256
#define OUT_DIM 512
#define MEM_LEN 131072
#define TOPK 16

#define ENC_PARTS 32
#define ROWS_PER_PART (IN_DIM / ENC_PARTS)   // 8

#define ROWS_PER_BLOCK 256
#define DIST_BLOCKS (MEM_LEN / ROWS_PER_BLOCK)   // 512
#define DIST_NT 512
#define DIST_ITERS (ROWS_PER_BLOCK / (DIST_NT / 32))  // 16

#define CAND_N (DIST_BLOCKS * TOPK)          // 8192
#define FIN_NT 256
#define PER_THREAD (CAND_N / FIN_NT)         // 32

__device__ float g_enc[OUT_DIM];
__device__ float g_part[ENC_PARTS * OUT_DIM];
__device__ float g_cand[CAND_N];

// ---------------------------------------------------------------------------
// Kernel A1: partial GEMV. Block p covers input rows [p*8, p*8+8).
// ---------------------------------------------------------------------------
__global__ void enc_partial_kernel(const float* __restrict__ data,
                                   const float* __restrict__ mean,
                                   const float* __restrict__ stdv,
                                   const float* __restrict__ W) {
    __shared__ float xn[ROWS_PER_PART];
    int t = threadIdx.x;              // 0..511 = output column
    int r0 = blockIdx.x * ROWS_PER_PART;
    if (t < ROWS_PER_PART) {
        int r = r0 + t;
        float s = stdv[r];
        xn[t] = (s == 0.0f) ? 0.0f : (data[r] - mean[r]) / s;
    }
    __syncthreads();
    float acc = 0.0f;
#pragma unroll
    for (int i = 0; i < ROWS_PER_PART; ++i)
        acc = fmaf(xn[i], W[(size_t)(r0 + i) * OUT_DIM + t], acc);
    g_part[blockIdx.x * OUT_DIM + t] = acc;
}

// ---------------------------------------------------------------------------
// Kernel A2: reduce partials, add bias, tanh.
// ---------------------------------------------------------------------------
__global__ void enc_finish_kernel(const float* __restrict__ b) {
    int t = threadIdx.x;
    float acc = b[t];
#pragma unroll
    for (int p = 0; p < ENC_PARTS; ++p)
        acc += g_part[p * OUT_DIM + t];
    g_enc[t] = tanhf(acc);
}

// ---------------------------------------------------------------------------
// Kernel B: fused dist + per-block top-16 (bitonic over 256 in shared).
// 512 blocks x 512 threads; 16 warps x 16 iterations = 256 rows/block.
// ---------------------------------------------------------------------------
__global__ void dist_topk_kernel(const float* __restrict__ memory) {
    __shared__ float se[OUT_DIM];
    __shared__ float sdist[ROWS_PER_BLOCK];

    int t = threadIdx.x;
    se[t] = g_enc[t];
    __syncthreads();

    int warp = t >> 5;
    int lane = t & 31;

    const float4* es = (const float4*)se;
    float4 e0 = es[0 * 32 + lane];
    float4 e1 = es[1 * 32 + lane];
    float4 e2 = es[2 * 32 + lane];
    float4 e3 = es[3 * 32 + lane];

    size_t row0 = (size_t)blockIdx.x * ROWS_PER_BLOCK;

#pragma unroll 2
    for (int it = 0; it < DIST_ITERS; ++it) {
        int r = it * 16 + warp;                       // 0..255
        const float4* m = (const float4*)(memory + (row0 + r) * OUT_DIM);
        float4 v0 = __ldg(&m[0 * 32 + lane]);
        float4 v1 = __ldg(&m[1 * 32 + lane]);
        float4 v2 = __ldg(&m[2 * 32 + lane]);
        float4 v3 = __ldg(&m[3 * 32 + lane]);

        float s = 0.0f;
        s += fabsf(v0.x - e0.x) + fabsf(v0.y - e0.y) + fabsf(v0.z - e0.z) + fabsf(v0.w - e0.w);
        s += fabsf(v1.x - e1.x) + fabsf(v1.y - e1.y) + fabsf(v1.z - e1.z) + fabsf(v1.w - e1.w);
        s += fabsf(v2.x - e2.x) + fabsf(v2.y - e2.y) + fabsf(v2.z - e2.z) + fabsf(v2.w - e2.w);
        s += fabsf(v3.x - e3.x) + fabsf(v3.y - e3.y) + fabsf(v3.z - e3.z) + fabsf(v3.w - e3.w);

#pragma unroll
        for (int o = 16; o > 0; o >>= 1)
            s += __shfl_xor_sync(0xFFFFFFFFu, s, o);

        if (lane == 0) sdist[r] = s;
    }
    __syncthreads();

    // bitonic sort ascending over 256 values
    for (int k = 2; k <= ROWS_PER_BLOCK; k <<= 1) {
        for (int j = k >> 1; j > 0; j >>= 1) {
            if (t < ROWS_PER_BLOCK) {
                int ixj = t ^ j;
                if (ixj > t) {
                    float a = sdist[t], c = sdist[ixj];
                    bool up = ((t & k) == 0);
                    if ((a > c) == up) { sdist[t] = c; sdist[ixj] = a; }
                }
            }
            __syncthreads();
        }
    }

    if (t < TOPK)
        g_cand[blockIdx.x * TOPK + t] = sdist[t];
}

// ---------------------------------------------------------------------------
// Kernel C: exact top-16 of 8192 candidates, fully branchless.
//  - per-thread sorted top-16 in registers (predicated bubble network)
//  - merge tree: c[i]=min(a[i],b[15-i]) -> bitonic clean (j=8,4,2,1)
// ---------------------------------------------------------------------------
__device__ __forceinline__ void bitonic_clean16(float* r) {
    // r is bitonic; after this it is sorted ascending.
#pragma unroll
    for (int j = 8; j > 0; j >>= 1) {
#pragma unroll
        for (int i = 0; i < TOPK; ++i) {
            if ((i & j) == 0 && (i ^ j) > i) {
                float lo = fminf(r[i], r[i ^ j]);
                float hi = fmaxf(r[i], r[i ^ j]);
                r[i] = lo; r[i ^ j] = hi;
            }
        }
    }
}

__global__ void final_topk_kernel(const float* __restrict__ exp_w,
                                  float* __restrict__ out) {
    __shared__ float sh[FIN_NT * TOPK];
    int tid = threadIdx.x;

    float r[TOPK];
#pragma unroll
    for (int i = 0; i < TOPK; ++i) r[i] = FLT_MAX;

    // per-thread branchless insertion over 32 candidates
#pragma unroll 4
    for (int c = 0; c < PER_THREAD; ++c) {
        float v = g_cand[tid + c * FIN_NT];
        bool ins = (v < r[TOPK - 1]);
        if (__any_sync(0xFFFFFFFFu, ins)) {
            r[TOPK - 1] = fminf(r[TOPK - 1], v);
            // one bubble pass restores sortedness (single new element)
#pragma unroll
            for (int i = TOPK - 1; i > 0; --i) {
                float lo = fminf(r[i - 1], r[i]);
                float hi = fmaxf(r[i - 1], r[i]);
                r[i - 1] = lo; r[i] = hi;
            }
        }
    }

    // merge tree over shared: 256 -> 1 sorted top-16 list
    for (int s = FIN_NT / 2; s >= 1; s >>= 1) {
        // active threads for NEXT level need peers' lists in shared
        if (tid >= s && tid < 2 * s) {
#pragma unroll
            for (int i = 0; i < TOPK; ++i) sh[tid * TOPK + i] = r[i];
        }
        __syncthreads();
        if (tid < s) {
            float b[TOPK];
#pragma unroll
            for (int i = 0; i < TOPK; ++i) b[i] = sh[(tid + s) * TOPK + i];
#pragma unroll
            for (int i = 0; i < TOPK; ++i) r[i] = fminf(r[i], b[TOPK - 1 - i]);
            bitonic_clean16(r);
        }
        __syncthreads();
    }

    if (tid == 0) {
        float num = 0.0f, den = 0.0f;
#pragma unroll
        for (int i = 0; i < TOPK; ++i) {
            float w = exp_w[i];
            num = fmaf(r[i], w, num);
            den += w;
        }
        out[0] = num / den;
    }
}

// ---------------------------------------------------------------------------
// Launch.
// Inputs: data[256], mean[256], std[256], memory[131072*512],
//         W[256*512], b[512], exp_w[16]  ->  out[1] float
// ---------------------------------------------------------------------------
extern "C" void kernel_launch(void* const* d_in, const int* in_sizes, int n_in,
                              void* d_out, int out_size) {
    const float* data   = (const float*)d_in[0];
    const float* mean   = (const float*)d_in[1];
    const float* stdv   = (const float*)d_in[2];
    const float* memory = (const float*)d_in[3];
    const float* W      = (const float*)d_in[4];
    const float* b      = (const float*)d_in[5];
    const float* exp_w  = (const float*)d_in[6];
    float* out = (float*)d_out;

    enc_partial_kernel<<<ENC_PARTS, OUT_DIM>>>(data, mean, stdv, W);
    enc_finish_kernel<<<1, OUT_DIM>>>(b);
    dist_topk_kernel<<<DIST_BLOCKS, DIST_NT>>>(memory);
    final_topk_kernel<<<1, FIN_NT>>>(exp_w, out);
}

// round 5
// speedup vs baseline: 1.6056x; 1.0354x over previous
#include <cuda_runtime.h>
#include <float.h>

#define IN_DIM 256
#define OUT_DIM 512
#define MEM_LEN 131072
#define TOPK 16

#define ENC_PARTS 32
#define ROWS_PER_PART (IN_DIM / ENC_PARTS)   // 8

#define ROWS_PER_BLOCK 256
#define DIST_BLOCKS (MEM_LEN / ROWS_PER_BLOCK)   // 512
#define DIST_NT 512
#define DIST_ITERS (ROWS_PER_BLOCK / (DIST_NT / 32))  // 16

#define CAND_N (DIST_BLOCKS * TOPK)          // 8192

__device__ float g_enc[OUT_DIM];
__device__ float g_part[ENC_PARTS * OUT_DIM];
__device__ float g_cand[CAND_N];
__device__ unsigned int g_ctr_enc;   // zero-initialized; reset after each use
__device__ unsigned int g_ctr_dist;

// ---------------------------------------------------------------------------
// sorted-ascending 16-list merge helper: r := 16 smallest of (r, b), sorted.
// r[i] = min(r[i], b[15-i]) yields a bitonic sequence of the 16 smallest;
// fixed 4-stage network cleans it. Fully branchless.
// ---------------------------------------------------------------------------
__device__ __forceinline__ void bitonic_clean16(float* r) {
#pragma unroll
    for (int j = 8; j > 0; j >>= 1) {
#pragma unroll
        for (int i = 0; i < TOPK; ++i) {
            if ((i & j) == 0 && (i ^ j) > i) {
                float lo = fminf(r[i], r[i ^ j]);
                float hi = fmaxf(r[i], r[i ^ j]);
                r[i] = lo; r[i ^ j] = hi;
            }
        }
    }
}

// ---------------------------------------------------------------------------
// Kernel 1: fused GEMV. 32 blocks x 512 threads; block p covers input rows
// [p*8, p*8+8). Last block to finish sums partials + bias, applies tanh.
// ---------------------------------------------------------------------------
__global__ void enc_kernel(const float* __restrict__ data,
                           const float* __restrict__ mean,
                           const float* __restrict__ stdv,
                           const float* __restrict__ W,
                           const float* __restrict__ b) {
    __shared__ float xn[ROWS_PER_PART];
    __shared__ unsigned int s_ticket;

    int t = threadIdx.x;              // 0..511 = output column
    int r0 = blockIdx.x * ROWS_PER_PART;
    if (t < ROWS_PER_PART) {
        int r = r0 + t;
        float s = stdv[r];
        xn[t] = (s == 0.0f) ? 0.0f : (data[r] - mean[r]) / s;
    }
    __syncthreads();
    float acc = 0.0f;
#pragma unroll
    for (int i = 0; i < ROWS_PER_PART; ++i)
        acc = fmaf(xn[i], W[(size_t)(r0 + i) * OUT_DIM + t], acc);
    g_part[blockIdx.x * OUT_DIM + t] = acc;

    // last-block-done: finisher sums the 32 partials
    __threadfence();
    __syncthreads();
    if (t == 0) s_ticket = atomicAdd(&g_ctr_enc, 1u);
    __syncthreads();
    if (s_ticket == ENC_PARTS - 1) {
        __threadfence();
        float sum = b[t];
#pragma unroll
        for (int p = 0; p < ENC_PARTS; ++p)
            sum += g_part[p * OUT_DIM + t];
        g_enc[t] = tanhf(sum);
        __threadfence();
        __syncthreads();
        if (t == 0) g_ctr_enc = 0u;   // reset for next graph replay
    }
}

// ---------------------------------------------------------------------------
// Kernel 2: fused dist + per-block top-16 + (last block) global merge & loss.
// 512 blocks x 512 threads; 16 warps x 16 iters = 256 rows/block.
// ---------------------------------------------------------------------------
__global__ void dist_topk_kernel(const float* __restrict__ memory,
                                 const float* __restrict__ exp_w,
                                 float* __restrict__ out) {
    __shared__ float se[OUT_DIM];
    __shared__ float sdist[ROWS_PER_BLOCK];
    __shared__ float smerge[DIST_NT * TOPK];   // 32 KB, for the finisher
    __shared__ unsigned int s_ticket;

    int t = threadIdx.x;
    se[t] = g_enc[t];
    __syncthreads();

    int warp = t >> 5;
    int lane = t & 31;

    const float4* es = (const float4*)se;
    float4 e0 = es[0 * 32 + lane];
    float4 e1 = es[1 * 32 + lane];
    float4 e2 = es[2 * 32 + lane];
    float4 e3 = es[3 * 32 + lane];

    size_t row0 = (size_t)blockIdx.x * ROWS_PER_BLOCK;

#pragma unroll 2
    for (int it = 0; it < DIST_ITERS; ++it) {
        int r = it * 16 + warp;                       // 0..255
        const float4* m = (const float4*)(memory + (row0 + r) * OUT_DIM);
        float4 v0 = __ldg(&m[0 * 32 + lane]);
        float4 v1 = __ldg(&m[1 * 32 + lane]);
        float4 v2 = __ldg(&m[2 * 32 + lane]);
        float4 v3 = __ldg(&m[3 * 32 + lane]);

        float s = 0.0f;
        s += fabsf(v0.x - e0.x) + fabsf(v0.y - e0.y) + fabsf(v0.z - e0.z) + fabsf(v0.w - e0.w);
        s += fabsf(v1.x - e1.x) + fabsf(v1.y - e1.y) + fabsf(v1.z - e1.z) + fabsf(v1.w - e1.w);
        s += fabsf(v2.x - e2.x) + fabsf(v2.y - e2.y) + fabsf(v2.z - e2.z) + fabsf(v2.w - e2.w);
        s += fabsf(v3.x - e3.x) + fabsf(v3.y - e3.y) + fabsf(v3.z - e3.z) + fabsf(v3.w - e3.w);

#pragma unroll
        for (int o = 16; o > 0; o >>= 1)
            s += __shfl_xor_sync(0xFFFFFFFFu, s, o);

        if (lane == 0) sdist[r] = s;
    }
    __syncthreads();

    // bitonic sort ascending over the block's 256 distances
    for (int k = 2; k <= ROWS_PER_BLOCK; k <<= 1) {
        for (int j = k >> 1; j > 0; j >>= 1) {
            if (t < ROWS_PER_BLOCK) {
                int ixj = t ^ j;
                if (ixj > t) {
                    float a = sdist[t], c = sdist[ixj];
                    bool up = ((t & k) == 0);
                    if ((a > c) == up) { sdist[t] = c; sdist[ixj] = a; }
                }
            }
            __syncthreads();
        }
    }

    if (t < TOPK)
        g_cand[blockIdx.x * TOPK + t] = sdist[t];   // sorted ascending

    // ---- last-block-done: global merge of 512 sorted 16-lists ----
    __threadfence();
    __syncthreads();
    if (t == 0) s_ticket = atomicAdd(&g_ctr_dist, 1u);
    __syncthreads();
    if (s_ticket != DIST_BLOCKS - 1) return;
    __threadfence();

    // each thread owns the sorted 16-list of one dist block (coalesced float4s)
    float r[TOPK];
    {
        const float4* c4 = (const float4*)(g_cand + t * TOPK);
        float4 a = c4[0], bq = c4[1], c = c4[2], d = c4[3];
        r[0]=a.x; r[1]=a.y; r[2]=a.z; r[3]=a.w;
        r[4]=bq.x; r[5]=bq.y; r[6]=bq.z; r[7]=bq.w;
        r[8]=c.x; r[9]=c.y; r[10]=c.z; r[11]=c.w;
        r[12]=d.x; r[13]=d.y; r[14]=d.z; r[15]=d.w;
    }

    // merge tree: 512 -> 1 sorted top-16
    for (int s = DIST_NT / 2; s >= 1; s >>= 1) {
        if (t >= s && t < 2 * s) {
#pragma unroll
            for (int i = 0; i < TOPK; ++i) smerge[t * TOPK + i] = r[i];
        }
        __syncthreads();
        if (t < s) {
            float b2[TOPK];
#pragma unroll
            for (int i = 0; i < TOPK; ++i) b2[i] = smerge[(t + s) * TOPK + i];
#pragma unroll
            for (int i = 0; i < TOPK; ++i) r[i] = fminf(r[i], b2[TOPK - 1 - i]);
            bitonic_clean16(r);
        }
        __syncthreads();
    }

    if (t == 0) {
        float num = 0.0f, den = 0.0f;
#pragma unroll
        for (int i = 0; i < TOPK; ++i) {
            float w = exp_w[i];
            num = fmaf(r[i], w, num);
            den += w;
        }
        out[0] = num / den;
        g_ctr_dist = 0u;   // reset for next graph replay
    }
}

// ---------------------------------------------------------------------------
// Launch.
// Inputs: data[256], mean[256], std[256], memory[131072*512],
//         W[256*512], b[512], exp_w[16]  ->  out[1] float
// ---------------------------------------------------------------------------
extern "C" void kernel_launch(void* const* d_in, const int* in_sizes, int n_in,
                              void* d_out, int out_size) {
    const float* data   = (const float*)d_in[0];
    const float* mean   = (const float*)d_in[1];
    const float* stdv   = (const float*)d_in[2];
    const float* memory = (const float*)d_in[3];
    const float* W      = (const float*)d_in[4];
    const float* b      = (const float*)d_in[5];
    const float* exp_w  = (const float*)d_in[6];
    float* out = (float*)d_out;

    enc_kernel<<<ENC_PARTS, OUT_DIM>>>(data, mean, stdv, W, b);
    dist_topk_kernel<<<DIST_BLOCKS, DIST_NT>>>(memory, exp_w, out);
}

// round 6
// speedup vs baseline: 1.8497x; 1.1520x over previous
#include <cuda_runtime.h>
#include <float.h>

#define IN_DIM 256
#define OUT_DIM 512
#define MEM_LEN 131072
#define TOPK 16

#define ENC_PARTS 64
#define ROWS_PER_PART (IN_DIM / ENC_PARTS)   // 4

#define ROWS_PER_BLOCK 256
#define DIST_BLOCKS (MEM_LEN / ROWS_PER_BLOCK)   // 512
#define DIST_NT 512                               // 16 warps
#define DIST_ITERS 16                              // rows per warp

#define CAND_N (DIST_BLOCKS * TOPK)          // 8192

__device__ float g_enc[OUT_DIM];
__device__ float g_part[ENC_PARTS * OUT_DIM];
__device__ float g_cand[CAND_N];
__device__ unsigned int g_ctr_enc;
__device__ unsigned int g_ctr_dist;

// ---------------------------------------------------------------------------
// bitonic clean of a register-resident 16-array (input bitonic -> sorted asc)
// ---------------------------------------------------------------------------
__device__ __forceinline__ void bitonic_clean16(float* r) {
#pragma unroll
    for (int j = 8; j > 0; j >>= 1) {
#pragma unroll
        for (int i = 0; i < TOPK; ++i) {
            if ((i & j) == 0 && (i ^ j) > i) {
                float lo = fminf(r[i], r[i ^ j]);
                float hi = fmaxf(r[i], r[i ^ j]);
                r[i] = lo; r[i ^ j] = hi;
            }
        }
    }
}

// merge own sorted-16 with XOR-partner's sorted-16 across lanes; all lanes
// end holding the sorted 16 smallest of the union. No divergence.
__device__ __forceinline__ void shfl_merge16(float* r, int off) {
#pragma unroll
    for (int i = 0; i < 8; ++i) {
        float ohi = __shfl_xor_sync(0xFFFFFFFFu, r[15 - i], off);
        float olo = __shfl_xor_sync(0xFFFFFFFFu, r[i], off);
        r[i]      = fminf(r[i], ohi);
        r[15 - i] = fminf(r[15 - i], olo);
    }
    bitonic_clean16(r);
}

// ---------------------------------------------------------------------------
// Kernel 1: fused GEMV. 64 blocks x 512 threads; block p covers input rows
// [p*4, p*4+4). Last block sums partials + bias, applies tanh.
// ---------------------------------------------------------------------------
__global__ void enc_kernel(const float* __restrict__ data,
                           const float* __restrict__ mean,
                           const float* __restrict__ stdv,
                           const float* __restrict__ W,
                           const float* __restrict__ b) {
    __shared__ float xn[ROWS_PER_PART];
    __shared__ unsigned int s_ticket;

    int t = threadIdx.x;              // 0..511 = output column
    int r0 = blockIdx.x * ROWS_PER_PART;
    if (t < ROWS_PER_PART) {
        int r = r0 + t;
        float s = stdv[r];
        xn[t] = (s == 0.0f) ? 0.0f : (data[r] - mean[r]) / s;
    }
    __syncthreads();
    float acc = 0.0f;
#pragma unroll
    for (int i = 0; i < ROWS_PER_PART; ++i)
        acc = fmaf(xn[i], W[(size_t)(r0 + i) * OUT_DIM + t], acc);
    g_part[blockIdx.x * OUT_DIM + t] = acc;

    __threadfence();
    __syncthreads();
    if (t == 0) s_ticket = atomicAdd(&g_ctr_enc, 1u);
    __syncthreads();
    if (s_ticket == ENC_PARTS - 1) {
        __threadfence();
        float sum = b[t];
#pragma unroll
        for (int p = 0; p < ENC_PARTS; ++p)
            sum += g_part[p * OUT_DIM + t];
        g_enc[t] = tanhf(sum);
        __threadfence();
        __syncthreads();
        if (t == 0) g_ctr_enc = 0u;
    }
}

// ---------------------------------------------------------------------------
// Kernel 2: dist + per-warp shuffle top-16 + per-block merge + global merge.
// 512 blocks x 512 threads, <=32 regs so 4 blocks/SM -> single full-chip wave.
// ---------------------------------------------------------------------------
__global__ void __launch_bounds__(DIST_NT, 4)
dist_topk_kernel(const float* __restrict__ memory,
                 const float* __restrict__ exp_w,
                 float* __restrict__ out) {
    __shared__ float se[OUT_DIM];           // enc, read at use (saves regs)
    __shared__ float swarp[16 * TOPK];      // per-warp sorted 16-lists
    __shared__ unsigned int s_ticket;

    int t = threadIdx.x;
    se[t] = g_enc[t];
    __syncthreads();

    int warp = t >> 5;
    int lane = t & 31;

    const float4* es = (const float4*)se;
    size_t row0 = (size_t)blockIdx.x * ROWS_PER_BLOCK;

    float my = FLT_MAX;   // lane l (<16) will hold dist(row l*16 + warp)

#pragma unroll 2
    for (int it = 0; it < DIST_ITERS; ++it) {
        int r = it * 16 + warp;                       // 0..255
        const float4* m = (const float4*)(memory + (row0 + r) * OUT_DIM);
        float4 v0 = __ldg(&m[0 * 32 + lane]);
        float4 v1 = __ldg(&m[1 * 32 + lane]);
        float4 v2 = __ldg(&m[2 * 32 + lane]);
        float4 v3 = __ldg(&m[3 * 32 + lane]);

        float4 e0 = es[0 * 32 + lane];
        float4 e1 = es[1 * 32 + lane];
        float4 e2 = es[2 * 32 + lane];
        float4 e3 = es[3 * 32 + lane];

        float s = 0.0f;
        s += fabsf(v0.x - e0.x) + fabsf(v0.y - e0.y) + fabsf(v0.z - e0.z) + fabsf(v0.w - e0.w);
        s += fabsf(v1.x - e1.x) + fabsf(v1.y - e1.y) + fabsf(v1.z - e1.z) + fabsf(v1.w - e1.w);
        s += fabsf(v2.x - e2.x) + fabsf(v2.y - e2.y) + fabsf(v2.z - e2.z) + fabsf(v2.w - e2.w);
        s += fabsf(v3.x - e3.x) + fabsf(v3.y - e3.y) + fabsf(v3.z - e3.z) + fabsf(v3.w - e3.w);

#pragma unroll
        for (int o = 16; o > 0; o >>= 1)
            s += __shfl_xor_sync(0xFFFFFFFFu, s, o);

        my = (lane == it) ? s : my;
    }

    // warp bitonic sort over 32 lane values (16 valid + 16 FLT_MAX), ascending
#pragma unroll
    for (int k = 2; k <= 32; k <<= 1) {
#pragma unroll
        for (int j = k >> 1; j > 0; j >>= 1) {
            float other = __shfl_xor_sync(0xFFFFFFFFu, my, j);
            bool up = ((lane & k) == 0);
            bool lower = ((lane & j) == 0);
            my = (lower == up) ? fminf(my, other) : fmaxf(my, other);
        }
    }
    if (lane < TOPK) swarp[warp * TOPK + lane] = my;
    __syncthreads();

    // warp 0 merges the 16 per-warp lists -> block's sorted top-16
    if (warp == 0) {
        float r[TOPK];
#pragma unroll
        for (int i = 0; i < TOPK; ++i)
            r[i] = (lane < 16) ? swarp[lane * TOPK + i] : FLT_MAX;
        shfl_merge16(r, 16);
        shfl_merge16(r, 8);
        shfl_merge16(r, 4);
        shfl_merge16(r, 2);
        shfl_merge16(r, 1);
        if (lane == 0) {
            float4* o4 = (float4*)(g_cand + blockIdx.x * TOPK);
            o4[0] = make_float4(r[0], r[1], r[2], r[3]);
            o4[1] = make_float4(r[4], r[5], r[6], r[7]);
            o4[2] = make_float4(r[8], r[9], r[10], r[11]);
            o4[3] = make_float4(r[12], r[13], r[14], r[15]);
        }
    }

    // ---- last-block-done: merge 512 sorted 16-lists + loss ----
    __threadfence();
    __syncthreads();
    if (t == 0) s_ticket = atomicAdd(&g_ctr_dist, 1u);
    __syncthreads();
    if (s_ticket != DIST_BLOCKS - 1) return;
    __threadfence();

    float r[TOPK];
    {
        const float4* c4 = (const float4*)(g_cand + t * TOPK);
        float4 a = c4[0], bq = c4[1], c = c4[2], d = c4[3];
        r[0]=a.x;  r[1]=a.y;  r[2]=a.z;  r[3]=a.w;
        r[4]=bq.x; r[5]=bq.y; r[6]=bq.z; r[7]=bq.w;
        r[8]=c.x;  r[9]=c.y;  r[10]=c.z; r[11]=c.w;
        r[12]=d.x; r[13]=d.y; r[14]=d.z; r[15]=d.w;
    }
    // in-warp: 32 lists -> 1 (all lanes hold warp result)
    shfl_merge16(r, 16);
    shfl_merge16(r, 8);
    shfl_merge16(r, 4);
    shfl_merge16(r, 2);
    shfl_merge16(r, 1);
    if (lane == 0) {
#pragma unroll
        for (int i = 0; i < TOPK; ++i) swarp[warp * TOPK + i] = r[i];
    }
    __syncthreads();
    if (warp == 0) {
#pragma unroll
        for (int i = 0; i < TOPK; ++i)
            r[i] = (lane < 16) ? swarp[lane * TOPK + i] : FLT_MAX;
        shfl_merge16(r, 16);
        shfl_merge16(r, 8);
        shfl_merge16(r, 4);
        shfl_merge16(r, 2);
        shfl_merge16(r, 1);
        if (lane == 0) {
            float num = 0.0f, den = 0.0f;
#pragma unroll
            for (int i = 0; i < TOPK; ++i) {
                float w = exp_w[i];
                num = fmaf(r[i], w, num);
                den += w;
            }
            out[0] = num / den;
            g_ctr_dist = 0u;
        }
    }
}

// ---------------------------------------------------------------------------
// Launch.
// Inputs: data[256], mean[256], std[256], memory[131072*512],
//         W[256*512], b[512], exp_w[16]  ->  out[1] float
// ---------------------------------------------------------------------------
extern "C" void kernel_launch(void* const* d_in, const int* in_sizes, int n_in,
                              void* d_out, int out_size) {
    const float* data   = (const float*)d_in[0];
    const float* mean   = (const float*)d_in[1];
    const float* stdv   = (const float*)d_in[2];
    const float* memory = (const float*)d_in[3];
    const float* W      = (const float*)d_in[4];
    const float* b      = (const float*)d_in[5];
    const float* exp_w  = (const float*)d_in[6];
    float* out = (float*)d_out;

    enc_kernel<<<ENC_PARTS, OUT_DIM>>>(data, mean, stdv, W, b);
    dist_topk_kernel<<<DIST_BLOCKS, DIST_NT>>>(memory, exp_w, out);
}